// round 1
// baseline (speedup 1.0000x reference)
#include <cuda_runtime.h>
#include <math.h>
#include <stdint.h>

#define BB 8
#define LL 2048
#define CC 256
#define HH 4
#define DDIM 64
#define RR (BB*LL)          // 16384 rows
#define C2 (2*CC)           // 512

// ---------------- scratch (no cudaMalloc allowed) ----------------
__device__ float g_qk0[BB*HH*LL*DDIM];
__device__ float g_qk1[BB*HH*LL*DDIM];
__device__ float g_v0 [BB*HH*LL*DDIM];
__device__ float g_v1 [BB*HH*LL*DDIM];
__device__ float g_m0 [BB*LL*CC];
__device__ float g_m1 [BB*LL*CC];
__device__ float g_p0 [BB*LL*CC];
__device__ float g_p1 [BB*LL*CC];
__device__ float g_h0 [RR*C2];
__device__ float g_h1 [RR*C2];

// ---------------- generic SGEMM: out[M,N] = concat(A0,A1)[M,K] @ W[K,N] (+bias)(*scale)(+res) ----------------
// BM=128, BN=128, BK=8, 256 threads, 8x8 micro-tile.
#define TBM 128
#define TBN 128
#define TBK 8

__global__ __launch_bounds__(256) void gemm_kernel(
    const float* __restrict__ A0, int K0,
    const float* __restrict__ A1, int K1,
    const float* __restrict__ W,
    const float* __restrict__ bias,
    const float* __restrict__ res,
    float* __restrict__ out,
    int N, float scale, int head_layout)
{
    const int K = K0 + K1;
    __shared__ float As[TBK][TBM + 4];
    __shared__ float Bs[TBK][TBN];

    const int tid = threadIdx.x;
    const int m0 = blockIdx.y * TBM;
    const int n0 = blockIdx.x * TBN;
    const int tr = tid >> 4;        // 0..15
    const int tc = tid & 15;        // 0..15

    const int a_row = tid >> 1;     // 0..127
    const int a_k   = (tid & 1) * 4;
    const int b_k   = tid >> 5;     // 0..7
    const int b_n   = (tid & 31) * 4;

    float acc[8][8];
    #pragma unroll
    for (int i = 0; i < 8; i++)
        #pragma unroll
        for (int j = 0; j < 8; j++) acc[i][j] = 0.f;

    for (int kt = 0; kt < K; kt += TBK) {
        // load A tile (store transposed)
        int kg = kt + a_k;
        const float* asrc;
        if (kg < K0) asrc = A0 + (size_t)(m0 + a_row) * K0 + kg;
        else         asrc = A1 + (size_t)(m0 + a_row) * K1 + (kg - K0);
        float4 av = *(const float4*)asrc;
        As[a_k + 0][a_row] = av.x;
        As[a_k + 1][a_row] = av.y;
        As[a_k + 2][a_row] = av.z;
        As[a_k + 3][a_row] = av.w;
        // load B tile
        float4 bv = *(const float4*)(W + (size_t)(kt + b_k) * N + n0 + b_n);
        *(float4*)&Bs[b_k][b_n] = bv;
        __syncthreads();

        #pragma unroll
        for (int kk = 0; kk < TBK; kk++) {
            float a_frag[8], b_frag[8];
            *(float4*)&a_frag[0] = *(float4*)&As[kk][tr * 8];
            *(float4*)&a_frag[4] = *(float4*)&As[kk][tr * 8 + 4];
            *(float4*)&b_frag[0] = *(float4*)&Bs[kk][tc * 8];
            *(float4*)&b_frag[4] = *(float4*)&Bs[kk][tc * 8 + 4];
            #pragma unroll
            for (int i = 0; i < 8; i++)
                #pragma unroll
                for (int j = 0; j < 8; j++)
                    acc[i][j] += a_frag[i] * b_frag[j];
        }
        __syncthreads();
    }

    #pragma unroll
    for (int i = 0; i < 8; i++) {
        int r = m0 + tr * 8 + i;
        #pragma unroll
        for (int j = 0; j < 8; j++) {
            int c = n0 + tc * 8 + j;
            float v = (acc[i][j] + bias[c]) * scale;
            if (res) v += res[(size_t)r * N + c];
            if (head_layout) {
                int b_ = r / LL, l = r % LL;
                int h  = c / DDIM, d = c % DDIM;
                out[(((size_t)(b_ * HH + h)) * LL + l) * DDIM + d] = v;
            } else {
                out[(size_t)r * N + c] = v;
            }
        }
    }
}

// ---------------- flash attention, both directions ----------------
// grid: (L/64, B*H, 2), 256 threads. q rows in regs, online softmax,
// P exchanged through per-warp smem rows. Out written merged (B,L,C).
#define FPAD 68

__global__ __launch_bounds__(256) void flash_kernel(
    const float* __restrict__ qk0, const float* __restrict__ qk1,
    const float* __restrict__ v0f, const float* __restrict__ v1f,
    float* __restrict__ m0out, float* __restrict__ m1out)
{
    extern __shared__ float sm[];
    float* qs = sm;
    float* ks = sm + 64 * FPAD;
    float* vs = ks + 64 * FPAD;
    float* ps = vs + 64 * FPAD;

    const int dir = blockIdx.z;
    const float* qp  = dir ? qk1 : qk0;
    const float* kp  = dir ? qk0 : qk1;
    const float* vp  = dir ? v0f : v1f;
    float*       outp = dir ? m1out : m0out;

    const int bh = blockIdx.y;
    const size_t base = (size_t)bh * LL * DDIM;
    const int q0 = blockIdx.x * 64;
    const int tid = threadIdx.x;

    // load q tile to smem
    #pragma unroll
    for (int rep = 0; rep < 4; rep++) {
        int idx = rep * 256 + tid;
        int row = idx >> 4;
        int dq  = (idx & 15) * 4;
        *(float4*)&qs[row * FPAD + dq] =
            *(const float4*)&qp[base + (size_t)(q0 + row) * DDIM + dq];
    }
    __syncthreads();

    const int row  = tid >> 2;
    const int quad = tid & 3;

    float qreg[64];
    #pragma unroll
    for (int kk = 0; kk < 64; kk += 4)
        *(float4*)&qreg[kk] = *(float4*)&qs[row * FPAD + kk];

    float m_i = -1e30f, l_i = 0.f;
    float o_acc[16];
    #pragma unroll
    for (int t = 0; t < 16; t++) o_acc[t] = 0.f;

    for (int k0 = 0; k0 < LL; k0 += 64) {
        __syncthreads();   // protects ks/vs/ps reuse across iterations
        #pragma unroll
        for (int rep = 0; rep < 4; rep++) {
            int idx = rep * 256 + tid;
            int r2  = idx >> 4;
            int dq  = (idx & 15) * 4;
            *(float4*)&ks[r2 * FPAD + dq] =
                *(const float4*)&kp[base + (size_t)(k0 + r2) * DDIM + dq];
            *(float4*)&vs[r2 * FPAD + dq] =
                *(const float4*)&vp[base + (size_t)(k0 + r2) * DDIM + dq];
        }
        __syncthreads();

        // S = q . k^T  (thread owns cols quad*16 .. quad*16+15 of its row)
        float s_vals[16];
        #pragma unroll
        for (int jj = 0; jj < 16; jj++) {
            int col = quad * 16 + jj;
            float dot = 0.f;
            #pragma unroll
            for (int kk = 0; kk < 64; kk += 4) {
                float4 kv = *(float4*)&ks[col * FPAD + kk];
                dot += qreg[kk]     * kv.x;
                dot += qreg[kk + 1] * kv.y;
                dot += qreg[kk + 2] * kv.z;
                dot += qreg[kk + 3] * kv.w;
            }
            s_vals[jj] = dot;
        }

        // online softmax (4 threads per row cooperate via shfl)
        float mt = s_vals[0];
        #pragma unroll
        for (int jj = 1; jj < 16; jj++) mt = fmaxf(mt, s_vals[jj]);
        mt = fmaxf(mt, __shfl_xor_sync(0xffffffffu, mt, 1));
        mt = fmaxf(mt, __shfl_xor_sync(0xffffffffu, mt, 2));
        float m_new = fmaxf(m_i, mt);
        float alpha = __expf(m_i - m_new);
        float psum = 0.f;
        #pragma unroll
        for (int jj = 0; jj < 16; jj++) {
            float p = __expf(s_vals[jj] - m_new);
            s_vals[jj] = p;
            psum += p;
        }
        psum += __shfl_xor_sync(0xffffffffu, psum, 1);
        psum += __shfl_xor_sync(0xffffffffu, psum, 2);
        l_i = l_i * alpha + psum;
        m_i = m_new;

        #pragma unroll
        for (int jj = 0; jj < 16; jj++)
            ps[row * FPAD + quad * 16 + jj] = s_vals[jj];
        #pragma unroll
        for (int t = 0; t < 16; t++) o_acc[t] *= alpha;
        __syncwarp();

        // O += P @ V  (thread owns d = quad*16 .. quad*16+15)
        #pragma unroll 8
        for (int j = 0; j < 64; j++) {
            float p = ps[row * FPAD + j];
            float4 va = *(float4*)&vs[j * FPAD + quad * 16 + 0];
            float4 vb = *(float4*)&vs[j * FPAD + quad * 16 + 4];
            float4 vc = *(float4*)&vs[j * FPAD + quad * 16 + 8];
            float4 vd = *(float4*)&vs[j * FPAD + quad * 16 + 12];
            o_acc[0]  += p * va.x; o_acc[1]  += p * va.y;
            o_acc[2]  += p * va.z; o_acc[3]  += p * va.w;
            o_acc[4]  += p * vb.x; o_acc[5]  += p * vb.y;
            o_acc[6]  += p * vb.z; o_acc[7]  += p * vb.w;
            o_acc[8]  += p * vc.x; o_acc[9]  += p * vc.y;
            o_acc[10] += p * vc.z; o_acc[11] += p * vc.w;
            o_acc[12] += p * vd.x; o_acc[13] += p * vd.y;
            o_acc[14] += p * vd.z; o_acc[15] += p * vd.w;
        }
    }

    float inv = 1.f / l_i;
    int b_ = bh >> 2;   // /H (H=4)
    int h  = bh & 3;
    size_t orow = ((size_t)(b_ * LL + q0 + row)) * CC + h * DDIM + quad * 16;
    #pragma unroll
    for (int t = 0; t < 16; t += 4) {
        float4 ov;
        ov.x = o_acc[t]     * inv;
        ov.y = o_acc[t + 1] * inv;
        ov.z = o_acc[t + 2] * inv;
        ov.w = o_acc[t + 3] * inv;
        *(float4*)&outp[orow + t] = ov;
    }
}

// ---------------- LayerNorm + exact GELU, rows of 512 ----------------
__global__ __launch_bounds__(256) void ln_gelu_kernel(
    float* __restrict__ h0, float* __restrict__ h1,
    const float* __restrict__ g, const float* __restrict__ bta)
{
    float* hp = blockIdx.y ? h1 : h0;
    const size_t rowoff = (size_t)blockIdx.x * C2;
    const int tid = threadIdx.x;
    const int lane = tid & 31, wid = tid >> 5;

    float2 v = *(float2*)&hp[rowoff + tid * 2];
    float s  = v.x + v.y;
    float sq = v.x * v.x + v.y * v.y;
    #pragma unroll
    for (int off = 16; off; off >>= 1) {
        s  += __shfl_xor_sync(0xffffffffu, s,  off);
        sq += __shfl_xor_sync(0xffffffffu, sq, off);
    }
    __shared__ float rs[8], rq[8];
    if (lane == 0) { rs[wid] = s; rq[wid] = sq; }
    __syncthreads();
    if (wid == 0) {
        s  = (lane < 8) ? rs[lane] : 0.f;
        sq = (lane < 8) ? rq[lane] : 0.f;
        #pragma unroll
        for (int off = 4; off; off >>= 1) {
            s  += __shfl_xor_sync(0xffffffffu, s,  off);
            sq += __shfl_xor_sync(0xffffffffu, sq, off);
        }
        if (lane == 0) { rs[0] = s; rq[0] = sq; }
    }
    __syncthreads();
    float mean = rs[0] * (1.f / 512.f);
    float var  = rq[0] * (1.f / 512.f) - mean * mean;
    float rstd = rsqrtf(var + 1e-5f);

    int c0 = tid * 2;
    float x0n = (v.x - mean) * rstd * g[c0]     + bta[c0];
    float x1n = (v.y - mean) * rstd * g[c0 + 1] + bta[c0 + 1];
    x0n = 0.5f * x0n * (1.f + erff(x0n * 0.70710678118654752f));
    x1n = 0.5f * x1n * (1.f + erff(x1n * 0.70710678118654752f));
    float2 o; o.x = x0n; o.y = x1n;
    *(float2*)&hp[rowoff + tid * 2] = o;
}

// ---------------- launch ----------------
extern "C" void kernel_launch(void* const* d_in, const int* in_sizes, int n_in,
                              void* d_out, int out_size)
{
    const float* x0   = (const float*)d_in[0];
    const float* x1   = (const float*)d_in[1];
    const float* Wqk  = (const float*)d_in[2];
    const float* bqk  = (const float*)d_in[3];
    const float* Wv   = (const float*)d_in[4];
    const float* bv   = (const float*)d_in[5];
    const float* Wout = (const float*)d_in[6];
    const float* bout = (const float*)d_in[7];
    const float* W1   = (const float*)d_in[8];
    const float* b1   = (const float*)d_in[9];
    const float* ln_g = (const float*)d_in[10];
    const float* ln_b = (const float*)d_in[11];
    const float* W2   = (const float*)d_in[12];
    const float* b2   = (const float*)d_in[13];
    float* out = (float*)d_out;

    float *p_qk0, *p_qk1, *p_v0, *p_v1, *p_m0, *p_m1, *p_p0, *p_p1, *p_h0, *p_h1;
    cudaGetSymbolAddress((void**)&p_qk0, g_qk0);
    cudaGetSymbolAddress((void**)&p_qk1, g_qk1);
    cudaGetSymbolAddress((void**)&p_v0,  g_v0);
    cudaGetSymbolAddress((void**)&p_v1,  g_v1);
    cudaGetSymbolAddress((void**)&p_m0,  g_m0);
    cudaGetSymbolAddress((void**)&p_m1,  g_m1);
    cudaGetSymbolAddress((void**)&p_p0,  g_p0);
    cudaGetSymbolAddress((void**)&p_p1,  g_p1);
    cudaGetSymbolAddress((void**)&p_h0,  g_h0);
    cudaGetSymbolAddress((void**)&p_h1,  g_h1);

    const int FLASH_SMEM = 4 * 64 * FPAD * sizeof(float); // 69632 B
    cudaFuncSetAttribute(flash_kernel,
                         cudaFuncAttributeMaxDynamicSharedMemorySize, FLASH_SMEM);

    const float qscale = 0.35355339059327373f; // 64^-0.25

    dim3 g256(CC / TBN, RR / TBM);   // (2,128)
    dim3 g512(C2 / TBN, RR / TBM);   // (4,128)

    // QK / V projections -> head layout
    gemm_kernel<<<g256, 256>>>(x0, CC, nullptr, 0, Wqk, bqk, nullptr, p_qk0, CC, qscale, 1);
    gemm_kernel<<<g256, 256>>>(x1, CC, nullptr, 0, Wqk, bqk, nullptr, p_qk1, CC, qscale, 1);
    gemm_kernel<<<g256, 256>>>(x0, CC, nullptr, 0, Wv,  bv,  nullptr, p_v0,  CC, 1.f,    1);
    gemm_kernel<<<g256, 256>>>(x1, CC, nullptr, 0, Wv,  bv,  nullptr, p_v1,  CC, 1.f,    1);

    // dual flash attention -> merged (B,L,C)
    dim3 fg(LL / 64, BB * HH, 2);
    flash_kernel<<<fg, 256, FLASH_SMEM>>>(p_qk0, p_qk1, p_v0, p_v1, p_m0, p_m1);

    // output projection
    gemm_kernel<<<g256, 256>>>(p_m0, CC, nullptr, 0, Wout, bout, nullptr, p_p0, CC, 1.f, 0);
    gemm_kernel<<<g256, 256>>>(p_m1, CC, nullptr, 0, Wout, bout, nullptr, p_p1, CC, 1.f, 0);

    // FFN-1 on virtual concat([x, mproj])
    gemm_kernel<<<g512, 256>>>(x0, CC, p_p0, CC, W1, b1, nullptr, p_h0, C2, 1.f, 0);
    gemm_kernel<<<g512, 256>>>(x1, CC, p_p1, CC, W1, b1, nullptr, p_h1, C2, 1.f, 0);

    // LayerNorm + GELU in place
    dim3 lg(RR, 2);
    ln_gelu_kernel<<<lg, 256>>>(p_h0, p_h1, ln_g, ln_b);

    // FFN-2 + residual -> outputs
    gemm_kernel<<<g256, 256>>>(p_h0, C2, nullptr, 0, W2, b2, x0, out,                 CC, 1.f, 0);
    gemm_kernel<<<g256, 256>>>(p_h1, C2, nullptr, 0, W2, b2, x1, out + (size_t)RR*CC, CC, 1.f, 0);
}

// round 2
// speedup vs baseline: 4.4556x; 4.4556x over previous
#include <cuda_runtime.h>
#include <math.h>
#include <stdint.h>

#define BB 8
#define LL 2048
#define CC 256
#define HH 4
#define DDIM 64
#define RR (BB*LL)          // 16384 rows
#define C2 (2*CC)           // 512

typedef unsigned long long u64;

// ---- packed f32x2 helpers ----
__device__ __forceinline__ u64 pk2(float x, float y) {
    u64 r; asm("mov.b64 %0,{%1,%2};" : "=l"(r) : "f"(x), "f"(y)); return r;
}
__device__ __forceinline__ u64 pk1(float x) { return pk2(x, x); }
__device__ __forceinline__ void upk2(u64 v, float& x, float& y) {
    asm("mov.b64 {%0,%1},%2;" : "=f"(x), "=f"(y) : "l"(v));
}
__device__ __forceinline__ u64 f2fma(u64 a, u64 b, u64 c) {
    u64 d; asm("fma.rn.f32x2 %0,%1,%2,%3;" : "=l"(d) : "l"(a), "l"(b), "l"(c)); return d;
}
__device__ __forceinline__ u64 f2mul(u64 a, u64 b) {
    u64 d; asm("mul.rn.f32x2 %0,%1,%2;" : "=l"(d) : "l"(a), "l"(b)); return d;
}

union F4U { float4 f4; u64 u[2]; };

// ---------------- scratch ----------------
__device__ float g_qk0[BB*HH*LL*DDIM];
__device__ float g_qk1[BB*HH*LL*DDIM];
__device__ float g_v0 [BB*HH*LL*DDIM];
__device__ float g_v1 [BB*HH*LL*DDIM];
__device__ float g_m0 [BB*LL*CC];
__device__ float g_m1 [BB*LL*CC];
__device__ float g_p0 [BB*LL*CC];
__device__ float g_p1 [BB*LL*CC];
__device__ float g_h0 [RR*C2];
__device__ float g_h1 [RR*C2];

// ---------------- SGEMM (f32x2 core) ----------------
#define TBM 128
#define TBN 128
#define TBK 8

__global__ __launch_bounds__(256, 2) void gemm_kernel(
    const float* __restrict__ A0, int K0,
    const float* __restrict__ A1, int K1,
    const float* __restrict__ W,
    const float* __restrict__ bias,
    const float* __restrict__ res,
    float* __restrict__ out,
    int N, float scale, int head_layout)
{
    const int K = K0 + K1;
    __shared__ float As[TBK][TBM + 4];
    __shared__ float Bs[TBK][TBN];

    const int tid = threadIdx.x;
    const int m0 = blockIdx.y * TBM;
    const int n0 = blockIdx.x * TBN;
    const int tr = tid >> 4;        // 0..15
    const int tc = tid & 15;        // 0..15

    const int a_row = tid >> 1;     // 0..127
    const int a_k   = (tid & 1) * 4;
    const int b_k   = tid >> 5;     // 0..7
    const int b_n   = (tid & 31) * 4;

    u64 acc[8][4];
    #pragma unroll
    for (int i = 0; i < 8; i++)
        #pragma unroll
        for (int p = 0; p < 4; p++) acc[i][p] = 0ULL;

    for (int kt = 0; kt < K; kt += TBK) {
        int kg = kt + a_k;
        const float* asrc;
        if (kg < K0) asrc = A0 + (size_t)(m0 + a_row) * K0 + kg;
        else         asrc = A1 + (size_t)(m0 + a_row) * K1 + (kg - K0);
        float4 av = *(const float4*)asrc;
        As[a_k + 0][a_row] = av.x;
        As[a_k + 1][a_row] = av.y;
        As[a_k + 2][a_row] = av.z;
        As[a_k + 3][a_row] = av.w;
        float4 bv = *(const float4*)(W + (size_t)(kt + b_k) * N + n0 + b_n);
        *(float4*)&Bs[b_k][b_n] = bv;
        __syncthreads();

        #pragma unroll
        for (int kk = 0; kk < TBK; kk++) {
            float af[8];
            *(float4*)&af[0] = *(float4*)&As[kk][tr * 8];
            *(float4*)&af[4] = *(float4*)&As[kk][tr * 8 + 4];
            F4U b0, b1;
            b0.f4 = *(float4*)&Bs[kk][tc * 8];
            b1.f4 = *(float4*)&Bs[kk][tc * 8 + 4];
            #pragma unroll
            for (int i = 0; i < 8; i++) {
                u64 ap = pk1(af[i]);
                acc[i][0] = f2fma(ap, b0.u[0], acc[i][0]);
                acc[i][1] = f2fma(ap, b0.u[1], acc[i][1]);
                acc[i][2] = f2fma(ap, b1.u[0], acc[i][2]);
                acc[i][3] = f2fma(ap, b1.u[1], acc[i][3]);
            }
        }
        __syncthreads();
    }

    #pragma unroll
    for (int i = 0; i < 8; i++) {
        int r = m0 + tr * 8 + i;
        float vv[8];
        #pragma unroll
        for (int p = 0; p < 4; p++) upk2(acc[i][p], vv[2 * p], vv[2 * p + 1]);
        #pragma unroll
        for (int j = 0; j < 8; j++) {
            int c = n0 + tc * 8 + j;
            float v = (vv[j] + bias[c]) * scale;
            if (res) v += res[(size_t)r * N + c];
            if (head_layout) {
                int b_ = r / LL, l = r % LL;
                int h  = c / DDIM, d = c % DDIM;
                out[(((size_t)(b_ * HH + h)) * LL + l) * DDIM + d] = v;
            } else {
                out[(size_t)r * N + c] = v;
            }
        }
    }
}

// ---------------- flash attention (register-tiled, f32x2) ----------------
// BQ=128 q-rows per block, BK=64 k-cols per tile, 256 threads.
// Thread tile: 8 q-rows (tr) x 4 cols (tc) for both S and O.
#define QT_STR 132
#define KT_STR 68
#define VS_STR 68
#define PT_STR 132
#define OFF_KT (64*QT_STR)              // 8448
#define OFF_VS (OFF_KT + 64*KT_STR)     // 12800
#define OFF_PT (OFF_VS + 64*VS_STR)     // 17152
#define FLASH_SMEM_FLOATS (OFF_PT + 64*PT_STR)   // 25600 floats = 102400 B

__global__ __launch_bounds__(256, 2) void flash_kernel(
    const float* __restrict__ qk0, const float* __restrict__ qk1,
    const float* __restrict__ v0f, const float* __restrict__ v1f,
    float* __restrict__ m0out, float* __restrict__ m1out)
{
    extern __shared__ float sm[];
    float* Qt = sm;             // [64][132]  (d-major, transposed)
    float* Kt = sm + OFF_KT;    // [64][68]
    float* Vs = sm + OFF_VS;    // [64][68]   (k-major, natural)
    float* Pt = sm + OFF_PT;    // [64][132]  (kcol-major, transposed P)

    const int dir = blockIdx.z;
    const float* qp = dir ? qk1 : qk0;
    const float* kp = dir ? qk0 : qk1;
    const float* vp = dir ? v0f : v1f;
    float*     outp = dir ? m1out : m0out;

    const int bh = blockIdx.y;
    const size_t base = (size_t)bh * LL * DDIM;
    const int q0 = blockIdx.x * 128;
    const int tid = threadIdx.x;
    const int tr = tid >> 4;     // 0..15
    const int tc = tid & 15;     // 0..15

    // load Q tile (128x64) transposed into Qt
    #pragma unroll
    for (int rep = 0; rep < 8; rep++) {
        int idx = rep * 256 + tid;
        int qrow = idx >> 4;
        int d4   = (idx & 15) * 4;
        float4 qv = *(const float4*)&qp[base + (size_t)(q0 + qrow) * DDIM + d4];
        Qt[(d4 + 0) * QT_STR + qrow] = qv.x;
        Qt[(d4 + 1) * QT_STR + qrow] = qv.y;
        Qt[(d4 + 2) * QT_STR + qrow] = qv.z;
        Qt[(d4 + 3) * QT_STR + qrow] = qv.w;
    }

    float m_i[8], l_i[8];
    u64 o[8][2];
    #pragma unroll
    for (int i = 0; i < 8; i++) {
        m_i[i] = -1e30f; l_i[i] = 0.f;
        o[i][0] = 0ULL; o[i][1] = 0ULL;
    }

    for (int k0 = 0; k0 < LL; k0 += 64) {
        __syncthreads();   // protect Kt/Vs/Pt reuse
        #pragma unroll
        for (int rep = 0; rep < 4; rep++) {
            int idx = rep * 256 + tid;
            int krow = idx >> 4;
            int d4   = (idx & 15) * 4;
            float4 kv = *(const float4*)&kp[base + (size_t)(k0 + krow) * DDIM + d4];
            Kt[(d4 + 0) * KT_STR + krow] = kv.x;
            Kt[(d4 + 1) * KT_STR + krow] = kv.y;
            Kt[(d4 + 2) * KT_STR + krow] = kv.z;
            Kt[(d4 + 3) * KT_STR + krow] = kv.w;
            float4 vv = *(const float4*)&vp[base + (size_t)(k0 + krow) * DDIM + d4];
            *(float4*)&Vs[krow * VS_STR + d4] = vv;
        }
        __syncthreads();

        // S = Q @ K^T  : thread tile 8 rows x 4 cols
        u64 s[8][2];
        #pragma unroll
        for (int i = 0; i < 8; i++) { s[i][0] = 0ULL; s[i][1] = 0ULL; }

        const float* qpt = Qt + tr * 8;
        const float* kpt = Kt + tc * 4;
        #pragma unroll 16
        for (int d = 0; d < 64; d++) {
            float af[8];
            *(float4*)&af[0] = *(float4*)&qpt[d * QT_STR];
            *(float4*)&af[4] = *(float4*)&qpt[d * QT_STR + 4];
            F4U bb; bb.f4 = *(float4*)&kpt[d * KT_STR];
            #pragma unroll
            for (int i = 0; i < 8; i++) {
                u64 ap = pk1(af[i]);
                s[i][0] = f2fma(ap, bb.u[0], s[i][0]);
                s[i][1] = f2fma(ap, bb.u[1], s[i][1]);
            }
        }

        // online softmax per row (row owned by 16 lanes tc)
        float sv[8][4];
        #pragma unroll
        for (int i = 0; i < 8; i++) {
            upk2(s[i][0], sv[i][0], sv[i][1]);
            upk2(s[i][1], sv[i][2], sv[i][3]);
        }
        #pragma unroll
        for (int i = 0; i < 8; i++) {
            float mt = fmaxf(fmaxf(sv[i][0], sv[i][1]), fmaxf(sv[i][2], sv[i][3]));
            mt = fmaxf(mt, __shfl_xor_sync(0xffffffffu, mt, 1));
            mt = fmaxf(mt, __shfl_xor_sync(0xffffffffu, mt, 2));
            mt = fmaxf(mt, __shfl_xor_sync(0xffffffffu, mt, 4));
            mt = fmaxf(mt, __shfl_xor_sync(0xffffffffu, mt, 8));
            float mn = fmaxf(m_i[i], mt);
            float al = __expf(m_i[i] - mn);
            float ps = 0.f;
            #pragma unroll
            for (int j = 0; j < 4; j++) {
                sv[i][j] = __expf(sv[i][j] - mn);
                ps += sv[i][j];
            }
            ps += __shfl_xor_sync(0xffffffffu, ps, 1);
            ps += __shfl_xor_sync(0xffffffffu, ps, 2);
            ps += __shfl_xor_sync(0xffffffffu, ps, 4);
            ps += __shfl_xor_sync(0xffffffffu, ps, 8);
            l_i[i] = l_i[i] * al + ps;
            m_i[i] = mn;
            u64 av = pk1(al);
            o[i][0] = f2mul(o[i][0], av);
            o[i][1] = f2mul(o[i][1], av);
        }

        // store P transposed: Pt[kcol][qrow]
        #pragma unroll
        for (int jj = 0; jj < 4; jj++) {
            float4 lo, hi;
            lo.x = sv[0][jj]; lo.y = sv[1][jj]; lo.z = sv[2][jj]; lo.w = sv[3][jj];
            hi.x = sv[4][jj]; hi.y = sv[5][jj]; hi.z = sv[6][jj]; hi.w = sv[7][jj];
            *(float4*)&Pt[(tc * 4 + jj) * PT_STR + tr * 8]     = lo;
            *(float4*)&Pt[(tc * 4 + jj) * PT_STR + tr * 8 + 4] = hi;
        }
        __syncthreads();

        // O += P @ V : thread tile 8 rows x 4 d-cols
        const float* ppt = Pt + tr * 8;
        const float* vpt = Vs + tc * 4;
        #pragma unroll 16
        for (int j = 0; j < 64; j++) {
            float af[8];
            *(float4*)&af[0] = *(float4*)&ppt[j * PT_STR];
            *(float4*)&af[4] = *(float4*)&ppt[j * PT_STR + 4];
            F4U bb; bb.f4 = *(float4*)&vpt[j * VS_STR];
            #pragma unroll
            for (int i = 0; i < 8; i++) {
                u64 ap = pk1(af[i]);
                o[i][0] = f2fma(ap, bb.u[0], o[i][0]);
                o[i][1] = f2fma(ap, bb.u[1], o[i][1]);
            }
        }
    }

    // epilogue: normalize and store merged (B,L,C)
    const int b_ = bh >> 2;
    const int h  = bh & 3;
    #pragma unroll
    for (int i = 0; i < 8; i++) {
        float inv = 1.f / l_i[i];
        float4 ov;
        upk2(o[i][0], ov.x, ov.y);
        upk2(o[i][1], ov.z, ov.w);
        ov.x *= inv; ov.y *= inv; ov.z *= inv; ov.w *= inv;
        size_t orow = ((size_t)(b_ * LL + q0 + tr * 8 + i)) * CC + h * DDIM + tc * 4;
        *(float4*)&outp[orow] = ov;
    }
}

// ---------------- LayerNorm + exact GELU, rows of 512 ----------------
__global__ __launch_bounds__(256) void ln_gelu_kernel(
    float* __restrict__ h0, float* __restrict__ h1,
    const float* __restrict__ g, const float* __restrict__ bta)
{
    float* hp = blockIdx.y ? h1 : h0;
    const size_t rowoff = (size_t)blockIdx.x * C2;
    const int tid = threadIdx.x;
    const int lane = tid & 31, wid = tid >> 5;

    float2 v = *(float2*)&hp[rowoff + tid * 2];
    float s  = v.x + v.y;
    float sq = v.x * v.x + v.y * v.y;
    #pragma unroll
    for (int off = 16; off; off >>= 1) {
        s  += __shfl_xor_sync(0xffffffffu, s,  off);
        sq += __shfl_xor_sync(0xffffffffu, sq, off);
    }
    __shared__ float rs[8], rq[8];
    if (lane == 0) { rs[wid] = s; rq[wid] = sq; }
    __syncthreads();
    if (wid == 0) {
        s  = (lane < 8) ? rs[lane] : 0.f;
        sq = (lane < 8) ? rq[lane] : 0.f;
        #pragma unroll
        for (int off = 4; off; off >>= 1) {
            s  += __shfl_xor_sync(0xffffffffu, s,  off);
            sq += __shfl_xor_sync(0xffffffffu, sq, off);
        }
        if (lane == 0) { rs[0] = s; rq[0] = sq; }
    }
    __syncthreads();
    float mean = rs[0] * (1.f / 512.f);
    float var  = rq[0] * (1.f / 512.f) - mean * mean;
    float rstd = rsqrtf(var + 1e-5f);

    int c0 = tid * 2;
    float x0n = (v.x - mean) * rstd * g[c0]     + bta[c0];
    float x1n = (v.y - mean) * rstd * g[c0 + 1] + bta[c0 + 1];
    x0n = 0.5f * x0n * (1.f + erff(x0n * 0.70710678118654752f));
    x1n = 0.5f * x1n * (1.f + erff(x1n * 0.70710678118654752f));
    float2 ov; ov.x = x0n; ov.y = x1n;
    *(float2*)&hp[rowoff + tid * 2] = ov;
}

// ---------------- launch ----------------
extern "C" void kernel_launch(void* const* d_in, const int* in_sizes, int n_in,
                              void* d_out, int out_size)
{
    const float* x0   = (const float*)d_in[0];
    const float* x1   = (const float*)d_in[1];
    const float* Wqk  = (const float*)d_in[2];
    const float* bqk  = (const float*)d_in[3];
    const float* Wv   = (const float*)d_in[4];
    const float* bv   = (const float*)d_in[5];
    const float* Wout = (const float*)d_in[6];
    const float* bout = (const float*)d_in[7];
    const float* W1   = (const float*)d_in[8];
    const float* b1   = (const float*)d_in[9];
    const float* ln_g = (const float*)d_in[10];
    const float* ln_b = (const float*)d_in[11];
    const float* W2   = (const float*)d_in[12];
    const float* b2   = (const float*)d_in[13];
    float* out = (float*)d_out;

    float *p_qk0, *p_qk1, *p_v0, *p_v1, *p_m0, *p_m1, *p_p0, *p_p1, *p_h0, *p_h1;
    cudaGetSymbolAddress((void**)&p_qk0, g_qk0);
    cudaGetSymbolAddress((void**)&p_qk1, g_qk1);
    cudaGetSymbolAddress((void**)&p_v0,  g_v0);
    cudaGetSymbolAddress((void**)&p_v1,  g_v1);
    cudaGetSymbolAddress((void**)&p_m0,  g_m0);
    cudaGetSymbolAddress((void**)&p_m1,  g_m1);
    cudaGetSymbolAddress((void**)&p_p0,  g_p0);
    cudaGetSymbolAddress((void**)&p_p1,  g_p1);
    cudaGetSymbolAddress((void**)&p_h0,  g_h0);
    cudaGetSymbolAddress((void**)&p_h1,  g_h1);

    const int FLASH_SMEM = FLASH_SMEM_FLOATS * sizeof(float); // 102400 B
    cudaFuncSetAttribute(flash_kernel,
                         cudaFuncAttributeMaxDynamicSharedMemorySize, FLASH_SMEM);

    const float qscale = 0.35355339059327373f; // 64^-0.25

    dim3 g256(CC / TBN, RR / TBM);   // (2,128)
    dim3 g512(C2 / TBN, RR / TBM);   // (4,128)

    // QK / V projections -> head layout
    gemm_kernel<<<g256, 256>>>(x0, CC, nullptr, 0, Wqk, bqk, nullptr, p_qk0, CC, qscale, 1);
    gemm_kernel<<<g256, 256>>>(x1, CC, nullptr, 0, Wqk, bqk, nullptr, p_qk1, CC, qscale, 1);
    gemm_kernel<<<g256, 256>>>(x0, CC, nullptr, 0, Wv,  bv,  nullptr, p_v0,  CC, 1.f,    1);
    gemm_kernel<<<g256, 256>>>(x1, CC, nullptr, 0, Wv,  bv,  nullptr, p_v1,  CC, 1.f,    1);

    // dual flash attention -> merged (B,L,C)
    dim3 fg(LL / 128, BB * HH, 2);
    flash_kernel<<<fg, 256, FLASH_SMEM>>>(p_qk0, p_qk1, p_v0, p_v1, p_m0, p_m1);

    // output projection
    gemm_kernel<<<g256, 256>>>(p_m0, CC, nullptr, 0, Wout, bout, nullptr, p_p0, CC, 1.f, 0);
    gemm_kernel<<<g256, 256>>>(p_m1, CC, nullptr, 0, Wout, bout, nullptr, p_p1, CC, 1.f, 0);

    // FFN-1 on virtual concat([x, mproj])
    gemm_kernel<<<g512, 256>>>(x0, CC, p_p0, CC, W1, b1, nullptr, p_h0, C2, 1.f, 0);
    gemm_kernel<<<g512, 256>>>(x1, CC, p_p1, CC, W1, b1, nullptr, p_h1, C2, 1.f, 0);

    // LayerNorm + GELU in place
    dim3 lg(RR, 2);
    ln_gelu_kernel<<<lg, 256>>>(p_h0, p_h1, ln_g, ln_b);

    // FFN-2 + residual -> outputs
    gemm_kernel<<<g256, 256>>>(p_h0, C2, nullptr, 0, W2, b2, x0, out,                 CC, 1.f, 0);
    gemm_kernel<<<g256, 256>>>(p_h1, C2, nullptr, 0, W2, b2, x1, out + (size_t)RR*CC, CC, 1.f, 0);
}

// round 4
// speedup vs baseline: 6.2918x; 1.4121x over previous
#include <cuda_runtime.h>
#include <cuda_bf16.h>
#include <math.h>
#include <stdint.h>

#define BB 8
#define LL 2048
#define CC 256
#define HH 4
#define DDIM 64
#define RR (BB*LL)          // 16384
#define C2 (2*CC)           // 512

typedef unsigned long long u64;
typedef unsigned int u32;
typedef __nv_bfloat16 bf16;

// ---- packed f32x2 helpers (flash) ----
__device__ __forceinline__ u64 pk2(float x, float y) {
    u64 r; asm("mov.b64 %0,{%1,%2};" : "=l"(r) : "f"(x), "f"(y)); return r;
}
__device__ __forceinline__ u64 pk1(float x) { return pk2(x, x); }
__device__ __forceinline__ void upk2(u64 v, float& x, float& y) {
    asm("mov.b64 {%0,%1},%2;" : "=f"(x), "=f"(y) : "l"(v));
}
__device__ __forceinline__ u64 f2fma(u64 a, u64 b, u64 c) {
    u64 d; asm("fma.rn.f32x2 %0,%1,%2,%3;" : "=l"(d) : "l"(a), "l"(b), "l"(c)); return d;
}
__device__ __forceinline__ u64 f2mul(u64 a, u64 b) {
    u64 d; asm("mul.rn.f32x2 %0,%1,%2;" : "=l"(d) : "l"(a), "l"(b)); return d;
}
union F4U { float4 f4; u64 u[2]; };

__device__ __forceinline__ void split1(float x, bf16& h_, bf16& l_) {
    h_ = __float2bfloat16(x);
    l_ = __float2bfloat16(x - __bfloat162float(h_));
}

__device__ __forceinline__ u32 smem_u32(const void* p) {
    u32 a;
    asm("{ .reg .u64 t; cvta.to.shared.u64 t, %1; cvt.u32.u64 %0, t; }"
        : "=r"(a) : "l"(p));
    return a;
}

__device__ __forceinline__ void ldsm4(u32 addr, u32& r0, u32& r1, u32& r2, u32& r3) {
    asm volatile("ldmatrix.sync.aligned.m8n8.x4.shared.b16 {%0,%1,%2,%3}, [%4];"
                 : "=r"(r0), "=r"(r1), "=r"(r2), "=r"(r3) : "r"(addr));
}

__device__ __forceinline__ void mma_bf16(float* c, const u32* a, const u32* b) {
    asm volatile(
        "mma.sync.aligned.m16n8k16.row.col.f32.bf16.bf16.f32 "
        "{%0,%1,%2,%3},{%4,%5,%6,%7},{%8,%9},{%0,%1,%2,%3};"
        : "+f"(c[0]), "+f"(c[1]), "+f"(c[2]), "+f"(c[3])
        : "r"(a[0]), "r"(a[1]), "r"(a[2]), "r"(a[3]), "r"(b[0]), "r"(b[1]));
}

// ===================== scratch =====================
__device__ float g_qk0[BB*HH*LL*DDIM];
__device__ float g_qk1[BB*HH*LL*DDIM];
__device__ float g_v0 [BB*HH*LL*DDIM];
__device__ float g_v1 [BB*HH*LL*DDIM];
__device__ float g_h0 [RR*C2];
__device__ float g_h1 [RR*C2];

__device__ bf16 g_x0h[RR*CC], g_x0l[RR*CC], g_x1h[RR*CC], g_x1l[RR*CC];
__device__ bf16 g_m0h[RR*CC], g_m0l[RR*CC], g_m1h[RR*CC], g_m1l[RR*CC];
__device__ bf16 g_p0h[RR*CC], g_p0l[RR*CC], g_p1h[RR*CC], g_p1l[RR*CC];
__device__ bf16 g_h0h[RR*C2], g_h0l[RR*C2], g_h1h[RR*C2], g_h1l[RR*C2];

__device__ bf16 g_Wqkh[CC*CC], g_Wqkl[CC*CC];
__device__ bf16 g_Wvh [CC*CC], g_Wvl [CC*CC];
__device__ bf16 g_Woth[CC*CC], g_Wotl[CC*CC];
__device__ bf16 g_W1h [C2*C2], g_W1l [C2*C2];
__device__ bf16 g_W2h [CC*C2], g_W2l [CC*C2];   // [N=256][K=512]

// ===================== split f32 -> bf16 hi/lo =====================
__global__ __launch_bounds__(256) void split_kernel(
    const float* __restrict__ x, bf16* __restrict__ hi, bf16* __restrict__ lo, int n)
{
    int i = (blockIdx.x * 256 + threadIdx.x) * 4;
    if (i >= n) return;
    float4 v = *(const float4*)(x + i);
    bf16 h0, l0, h1, l1, h2, l2, h3, l3;
    split1(v.x, h0, l0); split1(v.y, h1, l1);
    split1(v.z, h2, l2); split1(v.w, h3, l3);
    __nv_bfloat162 ph0, ph1, pl0, pl1;
    ph0.x = h0; ph0.y = h1; ph1.x = h2; ph1.y = h3;
    pl0.x = l0; pl0.y = l1; pl1.x = l2; pl1.y = l3;
    uint2 uh, ul;
    uh.x = *(u32*)&ph0; uh.y = *(u32*)&ph1;
    ul.x = *(u32*)&pl0; ul.y = *(u32*)&pl1;
    *(uint2*)(hi + i) = uh;
    *(uint2*)(lo + i) = ul;
}

// ===================== transpose W [K,N] -> split [N,K] =====================
__global__ __launch_bounds__(256) void wsplit_kernel(
    const float* __restrict__ W, bf16* __restrict__ hi, bf16* __restrict__ lo,
    int K, int N)
{
    __shared__ float t[32][33];
    int nb = blockIdx.x * 32, kb = blockIdx.y * 32;
    int tx = threadIdx.x, ty0 = threadIdx.y;  // block (32,8)
    #pragma unroll
    for (int r = 0; r < 4; r++) {
        int ty = ty0 + r * 8;
        t[ty][tx] = W[(size_t)(kb + ty) * N + nb + tx];
    }
    __syncthreads();
    #pragma unroll
    for (int r = 0; r < 4; r++) {
        int ty = ty0 + r * 8;
        float v = t[tx][ty];  // = W[kb+tx][nb+ty]
        bf16 h_, l_;
        split1(v, h_, l_);
        size_t o = (size_t)(nb + ty) * K + kb + tx;
        hi[o] = h_; lo[o] = l_;
    }
}

// ===================== mma.sync split-bf16 GEMM =====================
// out[M,N] = (concat(A0,A1)[M,K] @ W[K,N] + bias)*scale (+res)
// A,W as bf16 hi/lo; W transposed [N,K]. CTA 128x128, K chunk 64.
// 8 warps: warp tile 64x32 (grid 2m x 4n).
// mode: 0 = f32 out, 1 = f32 head-layout, 2 = split bf16 out
// smem: Ah 16K | Al 16K | Bh 16K | Bl 16K  (rows of 64 bf16 = 128B, XOR-swizzled)
#define MG_SMEM (64*1024 + 128)

__global__ __launch_bounds__(256, 2) void mma_gemm(
    const bf16* __restrict__ a0h, const bf16* __restrict__ a0l, int K0,
    const bf16* __restrict__ a1h, const bf16* __restrict__ a1l, int K1,
    const bf16* __restrict__ bh, const bf16* __restrict__ bl,
    const float* __restrict__ bias,
    const float* __restrict__ res,
    float* __restrict__ outf,
    bf16* __restrict__ outh, bf16* __restrict__ outl,
    int N, float scale, int mode)
{
    extern __shared__ char dsm[];
    u32 sb0 = smem_u32(dsm);
    u32 sb  = (sb0 + 127) & ~127u;
    char* smp = dsm + (sb - sb0);

    const int tid  = threadIdx.x;
    const int wid  = tid >> 5;
    const int lane = tid & 31;

    const int m0 = blockIdx.y * 128;
    const int n0 = blockIdx.x * 128;
    const int KB = K0 + K1;
    const int nc0 = K0 >> 6;
    const int nc  = KB >> 6;

    const int wm = (wid >> 2) * 64;   // 0 / 64
    const int wn = (wid & 3) * 32;    // 0..96

    const u32 sAh = sb;
    const u32 sAl = sb + 16384;
    const u32 sBh = sb + 32768;
    const u32 sBl = sb + 49152;

    float acc[4][4][4];
    #pragma unroll
    for (int i = 0; i < 4; i++)
        #pragma unroll
        for (int j = 0; j < 4; j++)
            #pragma unroll
            for (int t = 0; t < 4; t++) acc[i][j][t] = 0.f;

    // precompute load indices
    const int ld_row = tid >> 3;      // 0..31 (x4 reps -> 128 rows)
    const int ld_ch  = tid & 7;

    for (int c = 0; c < nc; c++) {
        __syncthreads();
        const bf16 *Ah, *Al;
        int astr, koff;
        if (c < nc0) { Ah = a0h; Al = a0l; astr = K0; koff = c << 6; }
        else         { Ah = a1h; Al = a1l; astr = K1; koff = (c - nc0) << 6; }
        const int koffB = c << 6;

        #pragma unroll
        for (int i = 0; i < 4; i++) {
            int row = ld_row + i * 32;
            u32 off = (u32)(row * 128 + ((ld_ch ^ (row & 7)) << 4));
            *(uint4*)(smp + off) =
                *(const uint4*)(Ah + (size_t)(m0 + row) * astr + koff + ld_ch * 8);
            *(uint4*)(smp + 16384 + off) =
                *(const uint4*)(Al + (size_t)(m0 + row) * astr + koff + ld_ch * 8);
            *(uint4*)(smp + 32768 + off) =
                *(const uint4*)(bh + (size_t)(n0 + row) * KB + koffB + ld_ch * 8);
            *(uint4*)(smp + 49152 + off) =
                *(const uint4*)(bl + (size_t)(n0 + row) * KB + koffB + ld_ch * 8);
        }
        __syncthreads();

        #pragma unroll
        for (int ks = 0; ks < 4; ks++) {
            const int cidx = ks * 2 + (lane >> 4);

            // B fragments (hi and lo): 4 n8-frags each
            u32 bfh[4][2], bfl[4][2];
            #pragma unroll
            for (int g = 0; g < 2; g++) {
                int rb = wn + g * 16 + (lane & 15);
                u32 off = (u32)(rb * 128 + ((cidx ^ (rb & 7)) << 4));
                u32 r0, r1, r2, r3;
                ldsm4(sBh + off, r0, r1, r2, r3);
                bfh[2*g][0] = r0; bfh[2*g][1] = r2;
                bfh[2*g+1][0] = r1; bfh[2*g+1][1] = r3;
                ldsm4(sBl + off, r0, r1, r2, r3);
                bfl[2*g][0] = r0; bfl[2*g][1] = r2;
                bfl[2*g+1][0] = r1; bfl[2*g+1][1] = r3;
            }

            // A-hi fragments
            u32 af[4][4];
            #pragma unroll
            for (int mi = 0; mi < 4; mi++) {
                int ra = wm + mi * 16 + (lane & 15);
                u32 off = (u32)(ra * 128 + ((cidx ^ (ra & 7)) << 4));
                ldsm4(sAh + off, af[mi][0], af[mi][1], af[mi][2], af[mi][3]);
            }
            #pragma unroll
            for (int mi = 0; mi < 4; mi++)
                #pragma unroll
                for (int nj = 0; nj < 4; nj++)
                    mma_bf16(acc[mi][nj], af[mi], bfh[nj]);
            #pragma unroll
            for (int mi = 0; mi < 4; mi++)
                #pragma unroll
                for (int nj = 0; nj < 4; nj++)
                    mma_bf16(acc[mi][nj], af[mi], bfl[nj]);

            // A-lo fragments (reuse regs)
            #pragma unroll
            for (int mi = 0; mi < 4; mi++) {
                int ra = wm + mi * 16 + (lane & 15);
                u32 off = (u32)(ra * 128 + ((cidx ^ (ra & 7)) << 4));
                ldsm4(sAl + off, af[mi][0], af[mi][1], af[mi][2], af[mi][3]);
            }
            #pragma unroll
            for (int mi = 0; mi < 4; mi++)
                #pragma unroll
                for (int nj = 0; nj < 4; nj++)
                    mma_bf16(acc[mi][nj], af[mi], bfh[nj]);
        }
    }

    // ---------------- epilogue ----------------
    const int lr = lane >> 2;
    const int lc = (lane & 3) * 2;
    #pragma unroll
    for (int mi = 0; mi < 4; mi++) {
        #pragma unroll
        for (int half = 0; half < 2; half++) {
            int r = m0 + wm + mi * 16 + lr + half * 8;
            #pragma unroll
            for (int nj = 0; nj < 4; nj++) {
                int col = n0 + wn + nj * 8 + lc;
                float2 bv = *(const float2*)(bias + col);
                float v0 = (acc[mi][nj][half * 2]     + bv.x) * scale;
                float v1 = (acc[mi][nj][half * 2 + 1] + bv.y) * scale;
                if (mode == 1) {
                    int b_ = r >> 11, l = r & 2047;
                    int h  = col >> 6, d = col & 63;
                    size_t o = (((size_t)(b_ * HH + h)) * LL + l) * DDIM + d;
                    *(float2*)(outf + o) = make_float2(v0, v1);
                } else if (mode == 0) {
                    size_t o = (size_t)r * N + col;
                    if (res) {
                        float2 rv = *(const float2*)(res + o);
                        v0 += rv.x; v1 += rv.y;
                    }
                    *(float2*)(outf + o) = make_float2(v0, v1);
                } else {
                    size_t o = (size_t)r * N + col;
                    bf16 ha, la, hb, lb_;
                    split1(v0, ha, la);
                    split1(v1, hb, lb_);
                    __nv_bfloat162 th, tl;
                    th.x = ha; th.y = hb; tl.x = la; tl.y = lb_;
                    *(u32*)(outh + o) = *(u32*)&th;
                    *(u32*)(outl + o) = *(u32*)&tl;
                }
            }
        }
    }
}

// ===================== flash attention (f32x2, split-bf16 output) =====================
#define QT_STR 132
#define KT_STR 68
#define VS_STR 68
#define PT_STR 132
#define OFF_KT (64*QT_STR)
#define OFF_VS (OFF_KT + 64*KT_STR)
#define OFF_PT (OFF_VS + 64*VS_STR)
#define FLASH_SMEM_FLOATS (OFF_PT + 64*PT_STR)

__global__ __launch_bounds__(256, 2) void flash_kernel(
    const float* __restrict__ qk0, const float* __restrict__ qk1,
    const float* __restrict__ v0f, const float* __restrict__ v1f,
    bf16* __restrict__ m0h, bf16* __restrict__ m0l,
    bf16* __restrict__ m1h, bf16* __restrict__ m1l)
{
    extern __shared__ float sm[];
    float* Qt = sm;
    float* Kt = sm + OFF_KT;
    float* Vs = sm + OFF_VS;
    float* Pt = sm + OFF_PT;

    const int dir = blockIdx.z;
    const float* qp = dir ? qk1 : qk0;
    const float* kp = dir ? qk0 : qk1;
    const float* vp = dir ? v0f : v1f;
    bf16* oh = dir ? m1h : m0h;
    bf16* ol = dir ? m1l : m0l;

    const int bh = blockIdx.y;
    const size_t base = (size_t)bh * LL * DDIM;
    const int q0 = blockIdx.x * 128;
    const int tid = threadIdx.x;
    const int tr = tid >> 4;
    const int tc = tid & 15;

    #pragma unroll
    for (int rep = 0; rep < 8; rep++) {
        int idx = rep * 256 + tid;
        int qrow = idx >> 4;
        int d4   = (idx & 15) * 4;
        float4 qv = *(const float4*)&qp[base + (size_t)(q0 + qrow) * DDIM + d4];
        Qt[(d4 + 0) * QT_STR + qrow] = qv.x;
        Qt[(d4 + 1) * QT_STR + qrow] = qv.y;
        Qt[(d4 + 2) * QT_STR + qrow] = qv.z;
        Qt[(d4 + 3) * QT_STR + qrow] = qv.w;
    }

    float m_i[8], l_i[8];
    u64 o[8][2];
    #pragma unroll
    for (int i = 0; i < 8; i++) {
        m_i[i] = -1e30f; l_i[i] = 0.f;
        o[i][0] = 0ULL; o[i][1] = 0ULL;
    }

    for (int k0 = 0; k0 < LL; k0 += 64) {
        __syncthreads();
        #pragma unroll
        for (int rep = 0; rep < 4; rep++) {
            int idx = rep * 256 + tid;
            int krow = idx >> 4;
            int d4   = (idx & 15) * 4;
            float4 kv = *(const float4*)&kp[base + (size_t)(k0 + krow) * DDIM + d4];
            Kt[(d4 + 0) * KT_STR + krow] = kv.x;
            Kt[(d4 + 1) * KT_STR + krow] = kv.y;
            Kt[(d4 + 2) * KT_STR + krow] = kv.z;
            Kt[(d4 + 3) * KT_STR + krow] = kv.w;
            float4 vv = *(const float4*)&vp[base + (size_t)(k0 + krow) * DDIM + d4];
            *(float4*)&Vs[krow * VS_STR + d4] = vv;
        }
        __syncthreads();

        u64 s[8][2];
        #pragma unroll
        for (int i = 0; i < 8; i++) { s[i][0] = 0ULL; s[i][1] = 0ULL; }

        const float* qpt = Qt + tr * 8;
        const float* kpt = Kt + tc * 4;
        #pragma unroll 16
        for (int d = 0; d < 64; d++) {
            float af[8];
            *(float4*)&af[0] = *(float4*)&qpt[d * QT_STR];
            *(float4*)&af[4] = *(float4*)&qpt[d * QT_STR + 4];
            F4U bb; bb.f4 = *(float4*)&kpt[d * KT_STR];
            #pragma unroll
            for (int i = 0; i < 8; i++) {
                u64 ap = pk1(af[i]);
                s[i][0] = f2fma(ap, bb.u[0], s[i][0]);
                s[i][1] = f2fma(ap, bb.u[1], s[i][1]);
            }
        }

        float sv[8][4];
        #pragma unroll
        for (int i = 0; i < 8; i++) {
            upk2(s[i][0], sv[i][0], sv[i][1]);
            upk2(s[i][1], sv[i][2], sv[i][3]);
        }
        #pragma unroll
        for (int i = 0; i < 8; i++) {
            float mt = fmaxf(fmaxf(sv[i][0], sv[i][1]), fmaxf(sv[i][2], sv[i][3]));
            mt = fmaxf(mt, __shfl_xor_sync(0xffffffffu, mt, 1));
            mt = fmaxf(mt, __shfl_xor_sync(0xffffffffu, mt, 2));
            mt = fmaxf(mt, __shfl_xor_sync(0xffffffffu, mt, 4));
            mt = fmaxf(mt, __shfl_xor_sync(0xffffffffu, mt, 8));
            float mn = fmaxf(m_i[i], mt);
            float al = __expf(m_i[i] - mn);
            float ps = 0.f;
            #pragma unroll
            for (int j = 0; j < 4; j++) {
                sv[i][j] = __expf(sv[i][j] - mn);
                ps += sv[i][j];
            }
            ps += __shfl_xor_sync(0xffffffffu, ps, 1);
            ps += __shfl_xor_sync(0xffffffffu, ps, 2);
            ps += __shfl_xor_sync(0xffffffffu, ps, 4);
            ps += __shfl_xor_sync(0xffffffffu, ps, 8);
            l_i[i] = l_i[i] * al + ps;
            m_i[i] = mn;
            u64 av = pk1(al);
            o[i][0] = f2mul(o[i][0], av);
            o[i][1] = f2mul(o[i][1], av);
        }

        #pragma unroll
        for (int jj = 0; jj < 4; jj++) {
            float4 lo, hi;
            lo.x = sv[0][jj]; lo.y = sv[1][jj]; lo.z = sv[2][jj]; lo.w = sv[3][jj];
            hi.x = sv[4][jj]; hi.y = sv[5][jj]; hi.z = sv[6][jj]; hi.w = sv[7][jj];
            *(float4*)&Pt[(tc * 4 + jj) * PT_STR + tr * 8]     = lo;
            *(float4*)&Pt[(tc * 4 + jj) * PT_STR + tr * 8 + 4] = hi;
        }
        __syncthreads();

        const float* ppt = Pt + tr * 8;
        const float* vpt = Vs + tc * 4;
        #pragma unroll 16
        for (int j = 0; j < 64; j++) {
            float af[8];
            *(float4*)&af[0] = *(float4*)&ppt[j * PT_STR];
            *(float4*)&af[4] = *(float4*)&ppt[j * PT_STR + 4];
            F4U bb; bb.f4 = *(float4*)&vpt[j * VS_STR];
            #pragma unroll
            for (int i = 0; i < 8; i++) {
                u64 ap = pk1(af[i]);
                o[i][0] = f2fma(ap, bb.u[0], o[i][0]);
                o[i][1] = f2fma(ap, bb.u[1], o[i][1]);
            }
        }
    }

    const int b_ = bh >> 2;
    const int h  = bh & 3;
    #pragma unroll
    for (int i = 0; i < 8; i++) {
        float inv = 1.f / l_i[i];
        float ov[4];
        upk2(o[i][0], ov[0], ov[1]);
        upk2(o[i][1], ov[2], ov[3]);
        #pragma unroll
        for (int t = 0; t < 4; t++) ov[t] *= inv;
        size_t orow = ((size_t)(b_ * LL + q0 + tr * 8 + i)) * CC + h * DDIM + tc * 4;
        bf16 ha[4], la[4];
        #pragma unroll
        for (int t = 0; t < 4; t++) split1(ov[t], ha[t], la[t]);
        uint2 uh, ul;
        __nv_bfloat162 t0, t1;
        t0.x = ha[0]; t0.y = ha[1]; t1.x = ha[2]; t1.y = ha[3];
        uh.x = *(u32*)&t0; uh.y = *(u32*)&t1;
        t0.x = la[0]; t0.y = la[1]; t1.x = la[2]; t1.y = la[3];
        ul.x = *(u32*)&t0; ul.y = *(u32*)&t1;
        *(uint2*)(oh + orow) = uh;
        *(uint2*)(ol + orow) = ul;
    }
}

// ===================== LayerNorm + exact GELU -> split bf16 =====================
__global__ __launch_bounds__(256) void ln_gelu_kernel(
    const float* __restrict__ h0, const float* __restrict__ h1,
    bf16* __restrict__ h0h, bf16* __restrict__ h0l,
    bf16* __restrict__ h1h, bf16* __restrict__ h1l,
    const float* __restrict__ g, const float* __restrict__ bta)
{
    const float* hp = blockIdx.y ? h1 : h0;
    bf16* oh = blockIdx.y ? h1h : h0h;
    bf16* olo = blockIdx.y ? h1l : h0l;
    const size_t rowoff = (size_t)blockIdx.x * C2;
    const int tid = threadIdx.x;
    const int lane = tid & 31, wid = tid >> 5;

    float2 v = *(const float2*)&hp[rowoff + tid * 2];
    float s  = v.x + v.y;
    float sq = v.x * v.x + v.y * v.y;
    #pragma unroll
    for (int off = 16; off; off >>= 1) {
        s  += __shfl_xor_sync(0xffffffffu, s,  off);
        sq += __shfl_xor_sync(0xffffffffu, sq, off);
    }
    __shared__ float rs[8], rq[8];
    if (lane == 0) { rs[wid] = s; rq[wid] = sq; }
    __syncthreads();
    if (wid == 0) {
        s  = (lane < 8) ? rs[lane] : 0.f;
        sq = (lane < 8) ? rq[lane] : 0.f;
        #pragma unroll
        for (int off = 4; off; off >>= 1) {
            s  += __shfl_xor_sync(0xffffffffu, s,  off);
            sq += __shfl_xor_sync(0xffffffffu, sq, off);
        }
        if (lane == 0) { rs[0] = s; rq[0] = sq; }
    }
    __syncthreads();
    float mean = rs[0] * (1.f / 512.f);
    float var  = rq[0] * (1.f / 512.f) - mean * mean;
    float rstd = rsqrtf(var + 1e-5f);

    int c0 = tid * 2;
    float x0n = (v.x - mean) * rstd * g[c0]     + bta[c0];
    float x1n = (v.y - mean) * rstd * g[c0 + 1] + bta[c0 + 1];
    x0n = 0.5f * x0n * (1.f + erff(x0n * 0.70710678118654752f));
    x1n = 0.5f * x1n * (1.f + erff(x1n * 0.70710678118654752f));

    bf16 ha, la, hb, lb_;
    split1(x0n, ha, la);
    split1(x1n, hb, lb_);
    __nv_bfloat162 th, tl;
    th.x = ha; th.y = hb; tl.x = la; tl.y = lb_;
    *(u32*)(oh + rowoff + c0)  = *(u32*)&th;
    *(u32*)(olo + rowoff + c0) = *(u32*)&tl;
}

// ===================== launch =====================
extern "C" void kernel_launch(void* const* d_in, const int* in_sizes, int n_in,
                              void* d_out, int out_size)
{
    const float* x0   = (const float*)d_in[0];
    const float* x1   = (const float*)d_in[1];
    const float* Wqk  = (const float*)d_in[2];
    const float* bqk  = (const float*)d_in[3];
    const float* Wv   = (const float*)d_in[4];
    const float* bv   = (const float*)d_in[5];
    const float* Wout = (const float*)d_in[6];
    const float* bout = (const float*)d_in[7];
    const float* W1   = (const float*)d_in[8];
    const float* b1   = (const float*)d_in[9];
    const float* ln_g = (const float*)d_in[10];
    const float* ln_b = (const float*)d_in[11];
    const float* W2   = (const float*)d_in[12];
    const float* b2   = (const float*)d_in[13];
    float* out = (float*)d_out;

    float *p_qk0, *p_qk1, *p_v0, *p_v1, *p_h0, *p_h1;
    bf16 *px0h, *px0l, *px1h, *px1l;
    bf16 *pm0h, *pm0l, *pm1h, *pm1l;
    bf16 *pp0h, *pp0l, *pp1h, *pp1l;
    bf16 *ph0h, *ph0l, *ph1h, *ph1l;
    bf16 *pWqkh, *pWqkl, *pWvh, *pWvl, *pWoth, *pWotl, *pW1h, *pW1l, *pW2h, *pW2l;

    cudaGetSymbolAddress((void**)&p_qk0, g_qk0);
    cudaGetSymbolAddress((void**)&p_qk1, g_qk1);
    cudaGetSymbolAddress((void**)&p_v0,  g_v0);
    cudaGetSymbolAddress((void**)&p_v1,  g_v1);
    cudaGetSymbolAddress((void**)&p_h0,  g_h0);
    cudaGetSymbolAddress((void**)&p_h1,  g_h1);
    cudaGetSymbolAddress((void**)&px0h, g_x0h); cudaGetSymbolAddress((void**)&px0l, g_x0l);
    cudaGetSymbolAddress((void**)&px1h, g_x1h); cudaGetSymbolAddress((void**)&px1l, g_x1l);
    cudaGetSymbolAddress((void**)&pm0h, g_m0h); cudaGetSymbolAddress((void**)&pm0l, g_m0l);
    cudaGetSymbolAddress((void**)&pm1h, g_m1h); cudaGetSymbolAddress((void**)&pm1l, g_m1l);
    cudaGetSymbolAddress((void**)&pp0h, g_p0h); cudaGetSymbolAddress((void**)&pp0l, g_p0l);
    cudaGetSymbolAddress((void**)&pp1h, g_p1h); cudaGetSymbolAddress((void**)&pp1l, g_p1l);
    cudaGetSymbolAddress((void**)&ph0h, g_h0h); cudaGetSymbolAddress((void**)&ph0l, g_h0l);
    cudaGetSymbolAddress((void**)&ph1h, g_h1h); cudaGetSymbolAddress((void**)&ph1l, g_h1l);
    cudaGetSymbolAddress((void**)&pWqkh, g_Wqkh); cudaGetSymbolAddress((void**)&pWqkl, g_Wqkl);
    cudaGetSymbolAddress((void**)&pWvh,  g_Wvh);  cudaGetSymbolAddress((void**)&pWvl,  g_Wvl);
    cudaGetSymbolAddress((void**)&pWoth, g_Woth); cudaGetSymbolAddress((void**)&pWotl, g_Wotl);
    cudaGetSymbolAddress((void**)&pW1h,  g_W1h);  cudaGetSymbolAddress((void**)&pW1l,  g_W1l);
    cudaGetSymbolAddress((void**)&pW2h,  g_W2h);  cudaGetSymbolAddress((void**)&pW2l,  g_W2l);

    const int FLASH_SMEM = FLASH_SMEM_FLOATS * sizeof(float);
    cudaFuncSetAttribute(flash_kernel,
                         cudaFuncAttributeMaxDynamicSharedMemorySize, FLASH_SMEM);
    cudaFuncSetAttribute(mma_gemm,
                         cudaFuncAttributeMaxDynamicSharedMemorySize, MG_SMEM);

    const float qscale = 0.35355339059327373f; // 64^-0.25

    // ---- conversions ----
    split_kernel<<<RR * CC / 1024, 256>>>(x0, px0h, px0l, RR * CC);
    split_kernel<<<RR * CC / 1024, 256>>>(x1, px1h, px1l, RR * CC);
    wsplit_kernel<<<dim3(CC/32, CC/32), dim3(32,8)>>>(Wqk,  pWqkh, pWqkl, CC, CC);
    wsplit_kernel<<<dim3(CC/32, CC/32), dim3(32,8)>>>(Wv,   pWvh,  pWvl,  CC, CC);
    wsplit_kernel<<<dim3(CC/32, CC/32), dim3(32,8)>>>(Wout, pWoth, pWotl, CC, CC);
    wsplit_kernel<<<dim3(C2/32, C2/32), dim3(32,8)>>>(W1,   pW1h,  pW1l,  C2, C2);
    wsplit_kernel<<<dim3(CC/32, C2/32), dim3(32,8)>>>(W2,   pW2h,  pW2l,  C2, CC);

    dim3 g256(2, 128);
    dim3 g512(4, 128);

    // ---- QK / V projections -> head-layout f32 ----
    mma_gemm<<<g256, 256, MG_SMEM>>>(px0h, px0l, CC, nullptr, nullptr, 0,
        pWqkh, pWqkl, bqk, nullptr, p_qk0, nullptr, nullptr, CC, qscale, 1);
    mma_gemm<<<g256, 256, MG_SMEM>>>(px1h, px1l, CC, nullptr, nullptr, 0,
        pWqkh, pWqkl, bqk, nullptr, p_qk1, nullptr, nullptr, CC, qscale, 1);
    mma_gemm<<<g256, 256, MG_SMEM>>>(px0h, px0l, CC, nullptr, nullptr, 0,
        pWvh, pWvl, bv, nullptr, p_v0, nullptr, nullptr, CC, 1.f, 1);
    mma_gemm<<<g256, 256, MG_SMEM>>>(px1h, px1l, CC, nullptr, nullptr, 0,
        pWvh, pWvl, bv, nullptr, p_v1, nullptr, nullptr, CC, 1.f, 1);

    // ---- dual flash attention -> split bf16 merged ----
    dim3 fg(LL / 128, BB * HH, 2);
    flash_kernel<<<fg, 256, FLASH_SMEM>>>(p_qk0, p_qk1, p_v0, p_v1,
                                          pm0h, pm0l, pm1h, pm1l);

    // ---- output projection -> split bf16 ----
    mma_gemm<<<g256, 256, MG_SMEM>>>(pm0h, pm0l, CC, nullptr, nullptr, 0,
        pWoth, pWotl, bout, nullptr, nullptr, pp0h, pp0l, CC, 1.f, 2);
    mma_gemm<<<g256, 256, MG_SMEM>>>(pm1h, pm1l, CC, nullptr, nullptr, 0,
        pWoth, pWotl, bout, nullptr, nullptr, pp1h, pp1l, CC, 1.f, 2);

    // ---- FFN-1 on virtual concat([x, p]) -> f32 ----
    mma_gemm<<<g512, 256, MG_SMEM>>>(px0h, px0l, CC, pp0h, pp0l, CC,
        pW1h, pW1l, b1, nullptr, p_h0, nullptr, nullptr, C2, 1.f, 0);
    mma_gemm<<<g512, 256, MG_SMEM>>>(px1h, px1l, CC, pp1h, pp1l, CC,
        pW1h, pW1l, b1, nullptr, p_h1, nullptr, nullptr, C2, 1.f, 0);

    // ---- LayerNorm + GELU -> split bf16 ----
    dim3 lg(RR, 2);
    ln_gelu_kernel<<<lg, 256>>>(p_h0, p_h1, ph0h, ph0l, ph1h, ph1l, ln_g, ln_b);

    // ---- FFN-2 + residual -> outputs ----
    mma_gemm<<<g256, 256, MG_SMEM>>>(ph0h, ph0l, C2, nullptr, nullptr, 0,
        pW2h, pW2l, b2, x0, out, nullptr, nullptr, CC, 1.f, 0);
    mma_gemm<<<g256, 256, MG_SMEM>>>(ph1h, ph1l, C2, nullptr, nullptr, 0,
        pW2h, pW2l, b2, x1, out + (size_t)RR * CC, nullptr, nullptr, CC, 1.f, 0);
}